// round 2
// baseline (speedup 1.0000x reference)
#include <cuda_runtime.h>

// Problem constants
#define NN   64          // batch
#define CC   32          // channels in / out
#define VV   512         // graph nodes
#define LL   13          // time steps in
#define SS   3           // supports
#define LOUT 11          // time steps out (valid conv, Kt=3)
#define NB   22528       // NN * CC * LOUT, column index nb = n*352 + co*11 + l
#define KBIG 3072        // 6 * VV : fused diffusion K dimension

// Scratch (allocation-free rule: __device__ globals)
// g_U rows: r = j*512 + v, j=0..6.  j=0 holds u0 (identity block), j=1..6 are GEMM B rows.
__device__ __align__(16) float g_U[7 * VV * NB];      // ~323 MB
__device__ __align__(16) float g_Mcat[VV * KBIG];     // 6 MB: Mcat[w][ (j-1)*512 + v ]
__device__ __align__(16) float g_Wt[96 * 224];        // repacked conv weights Wt[(ci*3+kt)][j*32+co]

// ---------------------------------------------------------------------------
// Prep: copy A_s into Mcat odd-hop columns, repack W -> Wt
// ---------------------------------------------------------------------------
__global__ void prep_copy(const float* __restrict__ sup, const float* __restrict__ W) {
    int tid = blockIdx.x * blockDim.x + threadIdx.x;
    if (tid < SS * VV * VV) {
        int s = tid / (VV * VV);
        int r = tid - s * VV * VV;
        int w = r / VV, v = r - w * VV;
        // hop-1 block for support s sits at K columns [2s*512, 2s*512+512)
        g_Mcat[w * KBIG + 2 * s * VV + v] = sup[tid];
    }
    if (tid < 96 * 224) {
        int k96 = tid / 224;
        int jco = tid - k96 * 224;
        int j  = jco >> 5, co = jco & 31;
        int ci = k96 / 3,  kt = k96 - ci * 3;
        // original W layout: [co][j*32+ci][0][kt]
        g_Wt[tid] = W[(co * 224 + j * CC + ci) * 3 + kt];
    }
}

// ---------------------------------------------------------------------------
// A2 = A_s @ A_s  -> Mcat hop-2 columns [(2s+1)*512, +512)
// 64x64x16 tiles, 4x4 microtile, 256 threads (tiny: 0.8 GFLOP total)
// ---------------------------------------------------------------------------
__global__ __launch_bounds__(256) void a2k(const float* __restrict__ sup) {
    const int BM = 64, BN = 64, BK = 16;
    __shared__ float As[BK][BM + 4];
    __shared__ float Bs[BK][BN];
    int s  = blockIdx.z;
    int w0 = blockIdx.y * BM, u0 = blockIdx.x * BN;
    int t  = threadIdx.x;
    int ty = t >> 4, tx = t & 15;
    int ar = t >> 2, ac4 = t & 3;
    int br = t >> 4, bc  = t & 15;
    const float* A = sup + (size_t)s * VV * VV;

    float acc[4][4];
#pragma unroll
    for (int i = 0; i < 4; i++)
#pragma unroll
        for (int j = 0; j < 4; j++) acc[i][j] = 0.f;

    for (int k0 = 0; k0 < VV; k0 += BK) {
        float4 va = *reinterpret_cast<const float4*>(&A[(w0 + ar) * VV + k0 + ac4 * 4]);
        As[ac4 * 4 + 0][ar] = va.x;
        As[ac4 * 4 + 1][ar] = va.y;
        As[ac4 * 4 + 2][ar] = va.z;
        As[ac4 * 4 + 3][ar] = va.w;
        float4 vb = *reinterpret_cast<const float4*>(&A[(k0 + br) * VV + u0 + bc * 4]);
        *reinterpret_cast<float4*>(&Bs[br][bc * 4]) = vb;
        __syncthreads();
#pragma unroll
        for (int kk = 0; kk < BK; kk++) {
            float a[4], b[4];
            *reinterpret_cast<float4*>(&a[0]) = *reinterpret_cast<const float4*>(&As[kk][ty * 4]);
            *reinterpret_cast<float4*>(&b[0]) = *reinterpret_cast<const float4*>(&Bs[kk][tx * 4]);
#pragma unroll
            for (int i = 0; i < 4; i++)
#pragma unroll
                for (int j = 0; j < 4; j++) acc[i][j] += a[i] * b[j];
        }
        __syncthreads();
    }
#pragma unroll
    for (int i = 0; i < 4; i++)
#pragma unroll
        for (int j = 0; j < 4; j++)
            g_Mcat[(w0 + ty * 4 + i) * KBIG + (2 * s + 1) * VV + u0 + tx * 4 + j] = acc[i][j];
}

// ---------------------------------------------------------------------------
// Stage B: u_j[n,co,v,l] = sum_{ci,kt} Wt[(ci,kt)][(j,co)] * x[n,ci,v,l+kt]
// One block per (v,n). 224 threads, thread t = j*32+co. x rows hoisted to regs.
// ---------------------------------------------------------------------------
__global__ void stageb(const float* __restrict__ x) {
    __shared__ float xs[CC][LL];
    int v = blockIdx.x, n = blockIdx.y;
    int t = threadIdx.x;
    for (int i = t; i < CC * LL; i += 224) {
        int c = i / LL, l = i - c * LL;
        xs[c][l] = x[(((size_t)n * CC + c) * VV + v) * LL + l];
    }
    __syncthreads();

    float acc[LOUT];
#pragma unroll
    for (int l = 0; l < LOUT; l++) acc[l] = 0.f;

#pragma unroll 4
    for (int ci = 0; ci < CC; ci++) {
        float xr[LL];
#pragma unroll
        for (int l = 0; l < LL; l++) xr[l] = xs[ci][l];
#pragma unroll
        for (int kt = 0; kt < 3; kt++) {
            float w = g_Wt[(ci * 3 + kt) * 224 + t];
#pragma unroll
            for (int l = 0; l < LOUT; l++) acc[l] += w * xr[l + kt];
        }
    }
    int j = t >> 5, co = t & 31;
    float* dst = &g_U[(size_t)(j * VV + v) * NB + n * 352 + co * 11];
#pragma unroll
    for (int l = 0; l < LOUT; l++) dst[l] = acc[l];
}

// ---------------------------------------------------------------------------
// Stage C: y[w, nb] = u0[w, nb] + sum_k Mcat[w, k] * U[512 + k, nb] + b[co]
// 128x128x16 tiles, 8x8 microtile, 256 threads, double-buffered smem with
// register staging: LDG for tile k+1 issued before FFMA block of tile k,
// one __syncthreads per K-iteration. All dims divide exactly.
// ---------------------------------------------------------------------------
__global__ __launch_bounds__(256) void stagec(const float* __restrict__ bias,
                                              float* __restrict__ y) {
    const int BM = 128, BN = 128, BK = 16;
    const int NT = KBIG / BK;  // 192 K-tiles
    __shared__ float As[2][BK][BM + 4];
    __shared__ float Bs[2][BK][BN];
    int t   = threadIdx.x;
    int w0  = blockIdx.y * BM;
    int nb0 = blockIdx.x * BN;
    int ty = t >> 4, tx = t & 15;
    int ar = t >> 2, ac4 = t & 3;   // A tile: 128 rows x 16 cols, 2 float4 per thread
    int br = t >> 5, bc4 = t & 31;  // B tile: 16 rows x 128 cols, 2 float4 per thread

    const float* Aptr = &g_Mcat[(w0 + ar) * KBIG + ac4 * 4];          // rows ar, ar+64
    const float* Bptr = &g_U[(size_t)(VV + br) * NB + nb0 + bc4 * 4]; // rows br, br+8

    float acc[8][8];
#pragma unroll
    for (int i = 0; i < 8; i++)
#pragma unroll
        for (int j = 0; j < 8; j++) acc[i][j] = 0.f;

    float4 ra[2], rb[2];
    // preload tile 0 into registers
#pragma unroll
    for (int h = 0; h < 2; h++) {
        ra[h] = *reinterpret_cast<const float4*>(Aptr + (size_t)h * 64 * KBIG);
        rb[h] = *reinterpret_cast<const float4*>(Bptr + (size_t)h * 8 * NB);
    }

    for (int kt = 0; kt < NT; kt++) {
        int cur = kt & 1;
        // stage regs -> smem[cur]
#pragma unroll
        for (int h = 0; h < 2; h++) {
            int r = ar + h * 64;
            As[cur][ac4 * 4 + 0][r] = ra[h].x;
            As[cur][ac4 * 4 + 1][r] = ra[h].y;
            As[cur][ac4 * 4 + 2][r] = ra[h].z;
            As[cur][ac4 * 4 + 3][r] = ra[h].w;
            *reinterpret_cast<float4*>(&Bs[cur][br + h * 8][bc4 * 4]) = rb[h];
        }
        __syncthreads();

        // issue LDGs for tile kt+1 early (latency hidden under FFMA block)
        if (kt + 1 < NT) {
            const float* An = Aptr + (kt + 1) * BK;
            const float* Bn = Bptr + (size_t)(kt + 1) * BK * NB;
#pragma unroll
            for (int h = 0; h < 2; h++) {
                ra[h] = *reinterpret_cast<const float4*>(An + (size_t)h * 64 * KBIG);
                rb[h] = *reinterpret_cast<const float4*>(Bn + (size_t)h * 8 * NB);
            }
        }

#pragma unroll
        for (int kk = 0; kk < BK; kk++) {
            float a[8], b[8];
#pragma unroll
            for (int i = 0; i < 8; i += 4)
                *reinterpret_cast<float4*>(&a[i]) =
                    *reinterpret_cast<const float4*>(&As[cur][kk][ty * 8 + i]);
#pragma unroll
            for (int j = 0; j < 8; j += 4)
                *reinterpret_cast<float4*>(&b[j]) =
                    *reinterpret_cast<const float4*>(&Bs[cur][kk][tx * 8 + j]);
#pragma unroll
            for (int i = 0; i < 8; i++)
#pragma unroll
                for (int j = 0; j < 8; j++) acc[i][j] += a[i] * b[j];
        }
        __syncthreads();
    }

    // Epilogue: add identity block u0 and bias, scatter to NCHW output
#pragma unroll
    for (int j = 0; j < 8; j++) {
        int nb  = nb0 + tx * 8 + j;
        int n   = nb / 352;
        int rem = nb - n * 352;
        int co  = rem / 11;
        int l   = rem - co * 11;
        float bv = bias[co];
#pragma unroll
        for (int i = 0; i < 8; i++) {
            int w = w0 + ty * 8 + i;
            y[((size_t)(n * CC + co) * VV + w) * LOUT + l] =
                acc[i][j] + g_U[(size_t)w * NB + nb] + bv;
        }
    }
}

// ---------------------------------------------------------------------------
extern "C" void kernel_launch(void* const* d_in, const int* in_sizes, int n_in,
                              void* d_out, int out_size) {
    const float* x   = (const float*)d_in[0];  // [64,32,512,13]
    const float* sup = (const float*)d_in[1];  // [3,512,512]
    const float* W   = (const float*)d_in[2];  // [32,224,1,3]
    const float* b   = (const float*)d_in[3];  // [32]
    float* y = (float*)d_out;                  // [64,32,512,11]

    prep_copy<<<(SS * VV * VV + 255) / 256, 256>>>(sup, W);
    a2k<<<dim3(VV / 64, VV / 64, SS), 256>>>(sup);
    stageb<<<dim3(VV, NN), 224>>>(x);
    stagec<<<dim3(NB / 128, VV / 128), 256>>>(b, y);
}

// round 10
// speedup vs baseline: 2.2647x; 2.2647x over previous
#include <cuda_runtime.h>
#include <cuda_bf16.h>
#include <cstdint>

// Problem constants
#define NN   64
#define CC   32
#define VV   512
#define LL   13
#define SS   3
#define LOUT 11
#define NB   22528       // N*C*Lout, nb = n*352 + co*11 + l
#define KBIG 3072        // 6*512 fused diffusion K
#define NTILES 48        // KBIG / 64

// ---------------- device scratch (allocation-free rule) ----------------
__device__ __align__(16) float g_U[7 * VV * NB];                 // rows j*512+v; j=0 is u0
__device__ __align__(16) float g_Wt[96 * 224];                   // repacked conv weights
__device__ __align__(16) __nv_bfloat16 g_Ahi[VV * KBIG];         // Mcat hi  [w][k]
__device__ __align__(16) __nv_bfloat16 g_Alo[VV * KBIG];         // Mcat lo
__device__ __align__(16) __nv_bfloat16 g_Uthi[(size_t)NB * KBIG];// U^T hi  [nb][k]
__device__ __align__(16) __nv_bfloat16 g_Utlo[(size_t)NB * KBIG];// U^T lo  [nb][k]

// ---------------- helpers (baseline PTX only: sm_80-era ISA) ----------------
__device__ __forceinline__ uint32_t smem_u32(const void* p) {
    uint32_t a;
    asm("{ .reg .u64 t; cvta.to.shared.u64 t, %1; cvt.u32.u64 %0, t; }" : "=r"(a) : "l"(p));
    return a;
}
__device__ __forceinline__ uint32_t swz(uint32_t o) { return o ^ ((o >> 3) & 0x70); }
__device__ __forceinline__ void cpa16(uint32_t s, const void* g) {
    asm volatile("cp.async.cg.shared.global [%0], [%1], 16;" :: "r"(s), "l"(g));
}
#define CP_COMMIT() asm volatile("cp.async.commit_group;" ::: "memory")
#define CP_WAIT0()  asm volatile("cp.async.wait_group 0;" ::: "memory")

__device__ __forceinline__ void ldsm4(uint32_t* r, uint32_t addr) {
    asm volatile("ldmatrix.sync.aligned.m8n8.x4.shared.b16 {%0,%1,%2,%3}, [%4];"
        : "=r"(r[0]), "=r"(r[1]), "=r"(r[2]), "=r"(r[3]) : "r"(addr));
}
__device__ __forceinline__ void mma16816(float* c, const uint32_t* a, const uint32_t* b) {
    asm volatile("mma.sync.aligned.m16n8k16.row.col.f32.bf16.bf16.f32 "
        "{%0,%1,%2,%3},{%4,%5,%6,%7},{%8,%9},{%0,%1,%2,%3};"
        : "+f"(c[0]), "+f"(c[1]), "+f"(c[2]), "+f"(c[3])
        : "r"(a[0]), "r"(a[1]), "r"(a[2]), "r"(a[3]), "r"(b[0]), "r"(b[1]));
}

__device__ __forceinline__ void split_store(float v, __nv_bfloat16* hi,
                                            __nv_bfloat16* lo) {
    __nv_bfloat16 h = __float2bfloat16(v);
    *hi = h;
    *lo = __float2bfloat16(v - __bfloat162float(h));
}

// ---------------------------------------------------------------------------
// Prep: sup -> bf16 hi/lo hop-1 blocks of A; W -> Wt repack
// ---------------------------------------------------------------------------
__global__ void prep_copy(const float* __restrict__ sup, const float* __restrict__ W) {
    int tid = blockIdx.x * blockDim.x + threadIdx.x;
    if (tid < SS * VV * VV) {
        int s = tid / (VV * VV);
        int r = tid - s * VV * VV;
        int w = r / VV, v = r - w * VV;
        int idx = w * KBIG + 2 * s * VV + v;
        split_store(sup[tid], &g_Ahi[idx], &g_Alo[idx]);
    }
    if (tid < 96 * 224) {
        int k96 = tid / 224;
        int jco = tid - k96 * 224;
        int j = jco >> 5, co = jco & 31;
        int ci = k96 / 3, kt = k96 - ci * 3;
        g_Wt[tid] = W[(co * 224 + j * CC + ci) * 3 + kt];
    }
}

// ---------------------------------------------------------------------------
// A2 = A_s @ A_s -> bf16 hi/lo hop-2 blocks of A (tiny: 0.8 GFLOP)
// ---------------------------------------------------------------------------
__global__ __launch_bounds__(256) void a2k(const float* __restrict__ sup) {
    const int BM = 64, BN = 64, BK = 16;
    __shared__ float As[BK][BM + 4];
    __shared__ float Bs[BK][BN];
    int s = blockIdx.z;
    int w0 = blockIdx.y * BM, u0 = blockIdx.x * BN;
    int t = threadIdx.x;
    int ty = t >> 4, tx = t & 15;
    int ar = t >> 2, ac4 = t & 3;
    int br = t >> 4, bc = t & 15;
    const float* A = sup + (size_t)s * VV * VV;
    float acc[4][4];
#pragma unroll
    for (int i = 0; i < 4; i++)
#pragma unroll
        for (int j = 0; j < 4; j++) acc[i][j] = 0.f;
    for (int k0 = 0; k0 < VV; k0 += BK) {
        float4 va = *reinterpret_cast<const float4*>(&A[(w0 + ar) * VV + k0 + ac4 * 4]);
        As[ac4 * 4 + 0][ar] = va.x; As[ac4 * 4 + 1][ar] = va.y;
        As[ac4 * 4 + 2][ar] = va.z; As[ac4 * 4 + 3][ar] = va.w;
        float4 vb = *reinterpret_cast<const float4*>(&A[(k0 + br) * VV + u0 + bc * 4]);
        *reinterpret_cast<float4*>(&Bs[br][bc * 4]) = vb;
        __syncthreads();
#pragma unroll
        for (int kk = 0; kk < BK; kk++) {
            float a[4], b[4];
            *reinterpret_cast<float4*>(&a[0]) = *reinterpret_cast<const float4*>(&As[kk][ty * 4]);
            *reinterpret_cast<float4*>(&b[0]) = *reinterpret_cast<const float4*>(&Bs[kk][tx * 4]);
#pragma unroll
            for (int i = 0; i < 4; i++)
#pragma unroll
                for (int j = 0; j < 4; j++) acc[i][j] += a[i] * b[j];
        }
        __syncthreads();
    }
#pragma unroll
    for (int i = 0; i < 4; i++)
#pragma unroll
        for (int j = 0; j < 4; j++) {
            int idx = (w0 + ty * 4 + i) * KBIG + (2 * s + 1) * VV + u0 + tx * 4 + j;
            split_store(acc[i][j], &g_Ahi[idx], &g_Alo[idx]);
        }
}

// ---------------------------------------------------------------------------
// Stage B: temporal conv per (v,n); writes g_U fp32 (j=0 block = u0)
// ---------------------------------------------------------------------------
__global__ void stageb(const float* __restrict__ x) {
    __shared__ float xs[CC][LL];
    int v = blockIdx.x, n = blockIdx.y;
    int t = threadIdx.x;
    for (int i = t; i < CC * LL; i += 224) {
        int c = i / LL, l = i - c * LL;
        xs[c][l] = x[(((size_t)n * CC + c) * VV + v) * LL + l];
    }
    __syncthreads();
    float acc[LOUT];
#pragma unroll
    for (int l = 0; l < LOUT; l++) acc[l] = 0.f;
#pragma unroll 4
    for (int ci = 0; ci < CC; ci++) {
        float xr[LL];
#pragma unroll
        for (int l = 0; l < LL; l++) xr[l] = xs[ci][l];
#pragma unroll
        for (int kt = 0; kt < 3; kt++) {
            float w = g_Wt[(ci * 3 + kt) * 224 + t];
#pragma unroll
            for (int l = 0; l < LOUT; l++) acc[l] += w * xr[l + kt];
        }
    }
    int j = t >> 5, co = t & 31;
    float* dst = &g_U[(size_t)(j * VV + v) * NB + n * 352 + co * 11];
#pragma unroll
    for (int l = 0; l < LOUT; l++) dst[l] = acc[l];
}

// ---------------------------------------------------------------------------
// Transpose+convert: U[512+k][nb] fp32 -> Ut_hi/lo[nb][k] bf16
// ---------------------------------------------------------------------------
__global__ __launch_bounds__(256) void tconv() {
    __shared__ float s[32][129];
    int k0 = blockIdx.x * 32, nb0 = blockIdx.y * 128;
    int t = threadIdx.x;
#pragma unroll
    for (int i = 0; i < 16; i++) {
        int idx = t + 256 * i;
        int kr = idx >> 7, nc = idx & 127;
        s[kr][nc] = g_U[(size_t)(VV + k0 + kr) * NB + nb0 + nc];
    }
    __syncthreads();
#pragma unroll
    for (int i = 0; i < 16; i++) {
        int idx = t + 256 * i;
        int r = idx >> 5, kc = idx & 31;
        size_t o = (size_t)(nb0 + r) * KBIG + k0 + kc;
        split_store(s[kc][r], &g_Uthi[o], &g_Utlo[o]);
    }
}

// ---------------------------------------------------------------------------
// Stage C (mma.sync bf16 HMMA): y[w,nb] = u0 + sum_k A[w,k]*Ut[nb,k] + bias
// hi/lo split: acc += ahi*bhi + ahi*blo + alo*bhi  (drops ~2^-18 alo*blo).
// CTA 128x128, K-tile 64, cp.async double buffer (2 x 64KB stages).
// Stage layout: Ahi@0 Alo@16K Bhi@32K Blo@48K; each 128 rows x 128B, swizzled.
// 8 warps as 2x4; warp tile 64x32 = 4x4 m16n8 frags.
// Grid (VV/128 fast, NB/128): CTAs sharing a B tile adjacent -> B L2-resident.
// ---------------------------------------------------------------------------
__device__ __forceinline__ void tc_loads(uint32_t sb, int buf, int kt,
                                         int w0, int nb0, int tid) {
    int r0 = tid >> 3, kc8 = tid & 7;
    int k0 = kt * 64;
    uint32_t base = sb + buf * 65536;
    const __nv_bfloat16* Ah = &g_Ahi[(size_t)(w0 + r0) * KBIG + k0 + kc8 * 8];
    const __nv_bfloat16* Al = &g_Alo[(size_t)(w0 + r0) * KBIG + k0 + kc8 * 8];
    const __nv_bfloat16* Bh = &g_Uthi[(size_t)(nb0 + r0) * KBIG + k0 + kc8 * 8];
    const __nv_bfloat16* Bl = &g_Utlo[(size_t)(nb0 + r0) * KBIG + k0 + kc8 * 8];
#pragma unroll
    for (int i = 0; i < 4; i++) {
        uint32_t so = swz((r0 + 32 * i) * 128 + kc8 * 16);
        cpa16(base + so,         Ah + (size_t)(32 * i) * KBIG);
        cpa16(base + 16384 + so, Al + (size_t)(32 * i) * KBIG);
        cpa16(base + 32768 + so, Bh + (size_t)(32 * i) * KBIG);
        cpa16(base + 49152 + so, Bl + (size_t)(32 * i) * KBIG);
    }
}

__global__ __launch_bounds__(256, 1) void stagec_mma(const float* __restrict__ bias,
                                                     float* __restrict__ y) {
    extern __shared__ char smem[];
    uint32_t sb = smem_u32(smem);
    int tid = threadIdx.x, wid = tid >> 5, lane = tid & 31;
    int w0 = blockIdx.x * 128, nb0 = blockIdx.y * 128;  // w fast: B L2 reuse
    int wy = wid >> 2, wx = wid & 3;                    // warp tile origin (64x32)

    float acc[16][4];
#pragma unroll
    for (int i = 0; i < 16; i++)
#pragma unroll
        for (int j = 0; j < 4; j++) acc[i][j] = 0.f;

    // ldmatrix lane addressing (within a stage sub-tile, 128B rows, swizzled)
    // A (16x16 frag): lanes 0-15 rows, lanes 16-31 rows at k+8
    int a_row = (lane & 15);
    int a_kc = (lane >> 4);          // 0/1 -> +0/+16 bytes
    // B (two 8x16 n-tiles per ldmatrix.x4)
    int b_g = lane >> 3;
    int b_row = (lane & 7) + ((b_g >> 1) & 1) * 8;
    int b_kc = (b_g & 1);

    tc_loads(sb, 0, 0, w0, nb0, tid);
    CP_COMMIT();

    for (int kt = 0; kt < NTILES; kt++) {
        int buf = kt & 1;
        CP_WAIT0();
        __syncthreads();
        if (kt + 1 < NTILES) {
            tc_loads(sb, buf ^ 1, kt + 1, w0, nb0, tid);
            CP_COMMIT();
        }
        uint32_t base = sb + buf * 65536;
#pragma unroll
        for (int ks = 0; ks < 4; ks++) {
            uint32_t ah[4][4], al[4][4], bh[4][2], bl[4][2];
#pragma unroll
            for (int mt = 0; mt < 4; mt++) {
                uint32_t off = swz((wy * 64 + mt * 16 + a_row) * 128 + ks * 32 + a_kc * 16);
                ldsm4(ah[mt], base + off);
                ldsm4(al[mt], base + 16384 + off);
            }
#pragma unroll
            for (int h = 0; h < 2; h++) {
                uint32_t off = swz((wx * 32 + h * 16 + b_row) * 128 + ks * 32 + b_kc * 16);
                uint32_t rh[4], rl[4];
                ldsm4(rh, base + 32768 + off);
                ldsm4(rl, base + 49152 + off);
                bh[h * 2 + 0][0] = rh[0]; bh[h * 2 + 0][1] = rh[1];
                bh[h * 2 + 1][0] = rh[2]; bh[h * 2 + 1][1] = rh[3];
                bl[h * 2 + 0][0] = rl[0]; bl[h * 2 + 0][1] = rl[1];
                bl[h * 2 + 1][0] = rl[2]; bl[h * 2 + 1][1] = rl[3];
            }
#pragma unroll
            for (int mt = 0; mt < 4; mt++)
#pragma unroll
                for (int nt = 0; nt < 4; nt++) {
                    float* c = acc[mt * 4 + nt];
                    mma16816(c, ah[mt], bh[nt]);
                    mma16816(c, ah[mt], bl[nt]);
                    mma16816(c, al[mt], bh[nt]);
                }
        }
        __syncthreads();
    }

    // Epilogue: + u0 + bias, scatter to y[n][co][w][l]
    int r_base = w0 + wy * 64 + (lane >> 2);
    int c_base = nb0 + wx * 32 + (lane & 3) * 2;
#pragma unroll
    for (int mt = 0; mt < 4; mt++)
#pragma unroll
        for (int nt = 0; nt < 4; nt++) {
            const float* c = acc[mt * 4 + nt];
#pragma unroll
            for (int q = 0; q < 4; q++) {
                int w = r_base + mt * 16 + (q >> 1) * 8;
                int nb = c_base + nt * 8 + (q & 1);
                int n = nb / 352;
                int rem = nb - n * 352;
                int co = rem / 11;
                int l = rem - co * 11;
                y[((size_t)(n * CC + co) * VV + w) * LOUT + l] =
                    c[q] + g_U[(size_t)w * NB + nb] + bias[co];
            }
        }
}

// ---------------------------------------------------------------------------
extern "C" void kernel_launch(void* const* d_in, const int* in_sizes, int n_in,
                              void* d_out, int out_size) {
    const float* x   = (const float*)d_in[0];  // [64,32,512,13]
    const float* sup = (const float*)d_in[1];  // [3,512,512]
    const float* W   = (const float*)d_in[2];  // [32,224,1,3]
    const float* b   = (const float*)d_in[3];  // [32]
    float* y = (float*)d_out;                  // [64,32,512,11]

    cudaFuncSetAttribute(stagec_mma, cudaFuncAttributeMaxDynamicSharedMemorySize, 131072);

    prep_copy<<<(SS * VV * VV + 255) / 256, 256>>>(sup, W);
    a2k<<<dim3(VV / 64, VV / 64, SS), 256>>>(sup);
    stageb<<<dim3(VV, NN), 224>>>(x);
    tconv<<<dim3(KBIG / 32, NB / 128), 256>>>();
    stagec_mma<<<dim3(VV / 128, NB / 128), 256, 131072>>>(b, y);
}